// round 2
// baseline (speedup 1.0000x reference)
#include <cuda_runtime.h>

// StructuredPruningIF: integrate-and-fire over T=4 timesteps.
// Pure streaming (256MB read + 256MB write), HBM-bound.
// R2: 2 float4 lanes/thread (MLP=8), streaming cache hints (__ldcs/__stcs)
// since no data is ever re-referenced.

#define T_STEPS 4

__global__ __launch_bounds__(256) void if_kernel(
    const float4* __restrict__ x,
    const float* __restrict__ thresh,
    float4* __restrict__ out,
    int n4)          // spatial float4 count per timestep (also timestep stride)
{
    // Each thread handles 2 adjacent float4 lanes: i and i + blockDim (keeps
    // both warp accesses fully coalesced within consecutive 128B segments).
    int base = blockIdx.x * (blockDim.x * 2) + threadIdx.x;
    int i0 = base;
    int i1 = base + blockDim.x;

    const float thre = __ldg(thresh);
    const long s = n4;

    if (i1 < n4) {
        // 8 independent loads in flight
        float4 a0 = __ldcs(&x[0 * s + i0]);
        float4 b0 = __ldcs(&x[0 * s + i1]);
        float4 a1 = __ldcs(&x[1 * s + i0]);
        float4 b1 = __ldcs(&x[1 * s + i1]);
        float4 a2 = __ldcs(&x[2 * s + i0]);
        float4 b2 = __ldcs(&x[2 * s + i1]);
        float4 a3 = __ldcs(&x[3 * s + i0]);
        float4 b3 = __ldcs(&x[3 * s + i1]);

        float4 xa[T_STEPS] = {a0, a1, a2, a3};
        float4 xb[T_STEPS] = {b0, b1, b2, b3};

        float4 ma = make_float4(0.5f * thre, 0.5f * thre, 0.5f * thre, 0.5f * thre);
        float4 mb = ma;

#pragma unroll
        for (int t = 0; t < T_STEPS; t++) {
            float4 sa, sb;

            ma.x += xa[t].x; sa.x = (ma.x >= thre) ? thre : 0.0f; ma.x -= sa.x;
            ma.y += xa[t].y; sa.y = (ma.y >= thre) ? thre : 0.0f; ma.y -= sa.y;
            ma.z += xa[t].z; sa.z = (ma.z >= thre) ? thre : 0.0f; ma.z -= sa.z;
            ma.w += xa[t].w; sa.w = (ma.w >= thre) ? thre : 0.0f; ma.w -= sa.w;

            mb.x += xb[t].x; sb.x = (mb.x >= thre) ? thre : 0.0f; mb.x -= sb.x;
            mb.y += xb[t].y; sb.y = (mb.y >= thre) ? thre : 0.0f; mb.y -= sb.y;
            mb.z += xb[t].z; sb.z = (mb.z >= thre) ? thre : 0.0f; mb.z -= sb.z;
            mb.w += xb[t].w; sb.w = (mb.w >= thre) ? thre : 0.0f; mb.w -= sb.w;

            __stcs(&out[t * s + i0], sa);
            __stcs(&out[t * s + i1], sb);
        }
    } else if (i0 < n4) {
        // Tail: single lane (won't trigger for the bench shape, kept for safety)
        float4 xa[T_STEPS];
#pragma unroll
        for (int t = 0; t < T_STEPS; t++) xa[t] = __ldcs(&x[t * s + i0]);

        float4 ma = make_float4(0.5f * thre, 0.5f * thre, 0.5f * thre, 0.5f * thre);
#pragma unroll
        for (int t = 0; t < T_STEPS; t++) {
            float4 sa;
            ma.x += xa[t].x; sa.x = (ma.x >= thre) ? thre : 0.0f; ma.x -= sa.x;
            ma.y += xa[t].y; sa.y = (ma.y >= thre) ? thre : 0.0f; ma.y -= sa.y;
            ma.z += xa[t].z; sa.z = (ma.z >= thre) ? thre : 0.0f; ma.z -= sa.z;
            ma.w += xa[t].w; sa.w = (ma.w >= thre) ? thre : 0.0f; ma.w -= sa.w;
            __stcs(&out[t * s + i0], sa);
        }
    }
}

extern "C" void kernel_launch(void* const* d_in, const int* in_sizes, int n_in,
                              void* d_out, int out_size) {
    const float* x      = (const float*)d_in[0];   // [512,128,32,32]
    const float* thresh = (const float*)d_in[1];   // [1]
    float* out          = (float*)d_out;

    int total = in_sizes[0];            // 67,108,864
    int per_t = total / T_STEPS;        // 16,777,216
    int n4 = per_t / 4;                 // 4,194,304 float4 lanes

    int threads = 256;
    int per_block = threads * 2;
    int blocks = (n4 + per_block - 1) / per_block;  // 8192
    if_kernel<<<blocks, threads>>>((const float4*)x, thresh, (float4*)out, n4);
}